// round 2
// baseline (speedup 1.0000x reference)
#include <cuda_runtime.h>
#include <math_constants.h>

#define BATCH 16
#define NL 4097      // x0 rows
#define DL 1024
#define NMR 1025     // x1 rows
#define DM 512
#define NSR 4097     // x2 rows / output rows
#define DS 256
#define NP 4098      // att1p length

#define INV_DK1 (1.0f/22.0f)
#define INV_DK2 (1.0f/32.0f)

#define DBLK 9
#define DWARPS 10
#define DTHREADS 320
#define NWARP (DBLK*DWARPS)   // 90 warp-partials per batch

// ---- scratch layout (floats) ----
#define O_CLS_S   0
#define O_Q1      8192
#define O_U1      16384
#define O_CLS_M   24576
#define O_Q2      40960
#define O_U2      57344
#define O_S1      73728
#define O_A1      90128
#define O_ATT1P   106528
#define O_Y       172096
#define O_OV      188480
#define O_GS      204864
#define O_PM      208960
#define O_PZ      (O_PM + BATCH*NWARP)
#define O_PA1     (O_PZ + BATCH*NWARP)
#define O_PA2     (O_PA1 + BATCH*NWARP*DL)
#define SCRATCH_FLOATS (O_PA2 + BATCH*NWARP*DL)

__device__ float g_scratch[SCRATCH_FLOATS];

__device__ __forceinline__ float warpSum(float v) {
    v += __shfl_xor_sync(0xffffffffu, v, 16);
    v += __shfl_xor_sync(0xffffffffu, v, 8);
    v += __shfl_xor_sync(0xffffffffu, v, 4);
    v += __shfl_xor_sync(0xffffffffu, v, 2);
    v += __shfl_xor_sync(0xffffffffu, v, 1);
    return v;
}
__device__ __forceinline__ float warpMax(float v) {
    v = fmaxf(v, __shfl_xor_sync(0xffffffffu, v, 16));
    v = fmaxf(v, __shfl_xor_sync(0xffffffffu, v, 8));
    v = fmaxf(v, __shfl_xor_sync(0xffffffffu, v, 4));
    v = fmaxf(v, __shfl_xor_sync(0xffffffffu, v, 2));
    v = fmaxf(v, __shfl_xor_sync(0xffffffffu, v, 1));
    return v;
}

__global__ void zeroK(float* p, int n) {
    int i = blockIdx.x * blockDim.x + threadIdx.x;
    if (i < n) p[i] = 0.f;
}

// y[b,n] = bias[n] + sum_k x[b*xstride+k] * W[n*K+k]  (W row-major (N,K)); warp per n.
__global__ void matvecT(const float* __restrict__ x, size_t xstride,
                        const float* __restrict__ W, const float* __restrict__ bias,
                        float* __restrict__ y, int N, int K) {
    extern __shared__ float sx[];
    const int Kp = (K + 3) & ~3;
    for (int i = threadIdx.x; i < BATCH * Kp; i += blockDim.x) {
        int b = i / Kp, k = i - b * Kp;
        sx[i] = (k < K) ? x[(size_t)b * xstride + k] : 0.f;
    }
    __syncthreads();
    const int warp = threadIdx.x >> 5, lane = threadIdx.x & 31;
    const int K4 = K >> 2;
    const bool wal = ((K & 3) == 0);
    for (int n = blockIdx.x * 8 + warp; n < N; n += gridDim.x * 8) {
        const float* Wn = W + (size_t)n * K;
        float acc[BATCH];
#pragma unroll
        for (int b = 0; b < BATCH; b++) acc[b] = 0.f;
        for (int c = lane; c < K4; c += 32) {
            float4 w4;
            if (wal) w4 = ((const float4*)Wn)[c];
            else { w4.x = Wn[4*c]; w4.y = Wn[4*c+1]; w4.z = Wn[4*c+2]; w4.w = Wn[4*c+3]; }
#pragma unroll
            for (int b = 0; b < BATCH; b++) {
                float4 xv = *(const float4*)(sx + b * Kp + 4 * c);
                acc[b] = fmaf(xv.x, w4.x, fmaf(xv.y, w4.y, fmaf(xv.z, w4.z, fmaf(xv.w, w4.w, acc[b]))));
            }
        }
        for (int k = (K4 << 2) + lane; k < K; k += 32) {
            float w = Wn[k];
#pragma unroll
            for (int b = 0; b < BATCH; b++) acc[b] = fmaf(sx[b * Kp + k], w, acc[b]);
        }
#pragma unroll
        for (int b = 0; b < BATCH; b++) {
            float v = warpSum(acc[b]);
            if (lane == 0) y[(size_t)b * N + n] = v + (bias ? bias[n] : 0.f);
        }
    }
}

// y[b,n] += sum_k x[b*xstride+k] * W[k*N+n]  (contract over W's row index).
// grid (N/256, KSPLIT); y must be pre-zeroed; atomic accumulate across k-splits.
#define CTK 64
__global__ void matvecC(const float* __restrict__ x, size_t xstride,
                        const float* __restrict__ W,
                        float* __restrict__ y, int N, int K) {
    __shared__ float sx[BATCH * CTK];
    const int t = threadIdx.x;
    const int n = blockIdx.x * 256 + t;
    const int KC = K / gridDim.y;
    const int kbeg = blockIdx.y * KC, kend = kbeg + KC;
    float acc[BATCH];
#pragma unroll
    for (int b = 0; b < BATCH; b++) acc[b] = 0.f;
    for (int k0 = kbeg; k0 < kend; k0 += CTK) {
        for (int i = t; i < BATCH * CTK; i += 256) {
            int b = i >> 6, kk = i & (CTK - 1);
            sx[i] = x[(size_t)b * xstride + k0 + kk];
        }
        __syncthreads();
#pragma unroll 4
        for (int kk = 0; kk < CTK; kk++) {
            float w = W[(size_t)(k0 + kk) * N + n];
#pragma unroll
            for (int b = 0; b < BATCH; b++) acc[b] = fmaf(sx[b * CTK + kk], w, acc[b]);
        }
        __syncthreads();
    }
#pragma unroll
    for (int b = 0; b < BATCH; b++) atomicAdd(&y[(size_t)b * N + n], acc[b]);
}

// s1[b,r] = dot(row_r, u1[b])/22 ; row 0 = cls_s_proj, rows 1.. = x1[b,r,:]
__global__ void scores1(const float* __restrict__ x1) {
    const int b = blockIdx.y;
    const int warp = threadIdx.x >> 5, lane = threadIdx.x & 31;
    const int r = blockIdx.x * 8 + warp;
    if (r >= NMR) return;
    const float4* xr = (r == 0)
        ? (const float4*)(g_scratch + O_CLS_S + (size_t)b * DM)
        : (const float4*)(x1 + ((size_t)b * NMR + r) * DM);
    const float4* u = (const float4*)(g_scratch + O_U1 + (size_t)b * DM);
    float acc = 0.f;
#pragma unroll
    for (int i = 0; i < DM / 128; i++) {
        float4 xv = xr[lane + 32 * i];
        float4 uv = __ldg(&u[lane + 32 * i]);
        acc += xv.x * uv.x + xv.y * uv.y + xv.z * uv.z + xv.w * uv.w;
    }
    acc = warpSum(acc);
    if (lane == 0) g_scratch[O_S1 + (size_t)b * NMR + r] = acc * INV_DK1;
}

__global__ void softmax1() {
    const int b = blockIdx.x, t = threadIdx.x;
    const float* s = g_scratch + O_S1 + (size_t)b * NMR;
    float* a = g_scratch + O_A1 + (size_t)b * NMR;
    __shared__ float red[8];
    __shared__ float sv;
    float m = -CUDART_INF_F;
    for (int i = t; i < NMR; i += 256) m = fmaxf(m, s[i]);
    m = warpMax(m);
    if ((t & 31) == 0) red[t >> 5] = m;
    __syncthreads();
    if (t == 0) { float v = red[0]; for (int i = 1; i < 8; i++) v = fmaxf(v, red[i]); sv = v; }
    __syncthreads();
    const float M = sv;
    float z = 0.f;
    for (int i = t; i < NMR; i += 256) z += __expf(s[i] - M);
    z = warpSum(z);
    __syncthreads();
    if ((t & 31) == 0) red[t >> 5] = z;
    __syncthreads();
    if (t == 0) { float v = 0.f; for (int i = 0; i < 8; i++) v += red[i]; sv = v; }
    __syncthreads();
    const float inv = 1.f / sv;
    for (int i = t; i < NMR; i += 256) a[i] = __expf(s[i] - M) * inv;
}

// Fused single pass over x0: s2 = x·u2/32 with online softmax, plus a1 += att1p[1+r]*x.
__global__ void __launch_bounds__(DTHREADS, 1) bigpass(const float* __restrict__ x0) {
    __shared__ float4 su2[DL / 4];
    const int b = blockIdx.y;
    const int t = threadIdx.x;
    if (t < DL / 4) su2[t] = ((const float4*)(g_scratch + O_U2 + (size_t)b * DL))[t];
    __syncthreads();
    const int warp = t >> 5, lane = t & 31;
    const int wid = blockIdx.x * DWARPS + warp;
    const float* attp = g_scratch + O_ATT1P + (size_t)b * NP + 1;

    float4 a1v[8], a2v[8];
#pragma unroll
    for (int i = 0; i < 8; i++) {
        a1v[i] = make_float4(0.f, 0.f, 0.f, 0.f);
        a2v[i] = make_float4(0.f, 0.f, 0.f, 0.f);
    }
    float m = -CUDART_INF_F, Z = 0.f;

    for (int r = wid; r < NL; r += NWARP) {
        const float4* xr = (const float4*)(x0 + ((size_t)b * NL + r) * DL);
        float4 xv[8];
#pragma unroll
        for (int i = 0; i < 8; i++) xv[i] = xr[lane + 32 * i];
        float s = 0.f;
#pragma unroll
        for (int i = 0; i < 8; i++) {
            float4 uv = su2[lane + 32 * i];
            s += xv[i].x * uv.x + xv[i].y * uv.y + xv[i].z * uv.z + xv[i].w * uv.w;
        }
        s = warpSum(s) * INV_DK2;
        const float w1 = __ldg(attp + r);
        if (s > m) {              // warp-uniform
            const float sc = __expf(m - s);
            Z = fmaf(Z, sc, 1.f);
            m = s;
#pragma unroll
            for (int i = 0; i < 8; i++) {
                a2v[i].x = fmaf(a2v[i].x, sc, xv[i].x);
                a2v[i].y = fmaf(a2v[i].y, sc, xv[i].y);
                a2v[i].z = fmaf(a2v[i].z, sc, xv[i].z);
                a2v[i].w = fmaf(a2v[i].w, sc, xv[i].w);
            }
        } else {
            const float p = __expf(s - m);
            Z += p;
#pragma unroll
            for (int i = 0; i < 8; i++) {
                a2v[i].x = fmaf(p, xv[i].x, a2v[i].x);
                a2v[i].y = fmaf(p, xv[i].y, a2v[i].y);
                a2v[i].z = fmaf(p, xv[i].z, a2v[i].z);
                a2v[i].w = fmaf(p, xv[i].w, a2v[i].w);
            }
        }
#pragma unroll
        for (int i = 0; i < 8; i++) {
            a1v[i].x = fmaf(w1, xv[i].x, a1v[i].x);
            a1v[i].y = fmaf(w1, xv[i].y, a1v[i].y);
            a1v[i].z = fmaf(w1, xv[i].z, a1v[i].z);
            a1v[i].w = fmaf(w1, xv[i].w, a1v[i].w);
        }
    }
    const size_t base = ((size_t)b * NWARP + wid) * DL;
    float4* pa1 = (float4*)(g_scratch + O_PA1 + base);
    float4* pa2 = (float4*)(g_scratch + O_PA2 + base);
#pragma unroll
    for (int i = 0; i < 8; i++) { pa1[lane + 32 * i] = a1v[i]; pa2[lane + 32 * i] = a2v[i]; }
    if (lane == 0) {
        g_scratch[O_PM + b * NWARP + wid] = m;
        g_scratch[O_PZ + b * NWARP + wid] = Z;
    }
}

// Combine warp partials + cls_m_proj (k=0) row; produce y[b,:]
__global__ void finalize() {
    const int b = blockIdx.y;
    const int t = threadIdx.x;
    __shared__ float spm[NWARP], ssc[NWARP];
    __shared__ float red[8];
    __shared__ float sS0, sM, sZ;
    const float* cm = g_scratch + O_CLS_M + (size_t)b * DL;
    const float* u2 = g_scratch + O_U2 + (size_t)b * DL;
    // s0 = dot(cls_m_proj, u2)/32
    float part = 0.f;
    for (int i = t; i < DL; i += 256) part += cm[i] * u2[i];
    part = warpSum(part);
    if ((t & 31) == 0) red[t >> 5] = part;
    for (int i = t; i < NWARP; i += 256) spm[i] = g_scratch[O_PM + b * NWARP + i];
    __syncthreads();
    if (t == 0) {
        float s = 0.f;
        for (int i = 0; i < 8; i++) s += red[i];
        sS0 = s * INV_DK2;
        float M = sS0;
        for (int w = 0; w < NWARP; w++) M = fmaxf(M, spm[w]);
        sM = M;
    }
    __syncthreads();
    for (int i = t; i < NWARP; i += 256) ssc[i] = expf(spm[i] - sM);
    __syncthreads();
    if (t == 0) {
        float Z = expf(sS0 - sM);
        for (int w = 0; w < NWARP; w++) Z += g_scratch[O_PZ + b * NWARP + w] * ssc[w];
        sZ = Z;
    }
    __syncthreads();
    const int d = blockIdx.x * 256 + t;
    const float att1p0 = g_scratch[O_ATT1P + (size_t)b * NP];
    const float cmd = cm[d];
    float a1 = att1p0 * cmd;
    float a2 = expf(sS0 - sM) * cmd;
    const float* pa1 = g_scratch + O_PA1 + (size_t)b * NWARP * DL + d;
    const float* pa2 = g_scratch + O_PA2 + (size_t)b * NWARP * DL + d;
#pragma unroll 2
    for (int w = 0; w < NWARP; w++) {
        a1 += pa1[(size_t)w * DL];
        a2 = fmaf(ssc[w], pa2[(size_t)w * DL], a2);
    }
    g_scratch[O_Y + (size_t)b * DL + d] = 0.3f * a1 + 0.7f * (a2 / sZ);
}

__global__ void broadcastOut(float* __restrict__ out) {
    __shared__ float4 sg[64];
    const int b = blockIdx.y;
    if (threadIdx.x < 64)
        sg[threadIdx.x] = ((const float4*)(g_scratch + O_GS + (size_t)b * DS))[threadIdx.x];
    __syncthreads();
    const int total = NSR * (DS / 4);   // 262208 float4 per batch
    float4* ob = (float4*)out + (size_t)b * total;
    for (int i = blockIdx.x * 256 + threadIdx.x; i < total; i += 256 * 256)
        ob[i] = sg[i & 63];
}

extern "C" void kernel_launch(void* const* d_in, const int* in_sizes, int n_in,
                              void* d_out, int out_size) {
    (void)in_sizes; (void)n_in; (void)out_size;
    const float* x0     = (const float*)d_in[0];
    const float* x1     = (const float*)d_in[1];
    const float* x2     = (const float*)d_in[2];
    const float* f_s_w  = (const float*)d_in[3];
    const float* f_s_b  = (const float*)d_in[4];
    const float* f_m_w  = (const float*)d_in[5];
    const float* f_m_b  = (const float*)d_in[6];
    const float* Wq1    = (const float*)d_in[7];
    const float* Wk1    = (const float*)d_in[8];
    const float* Wq2    = (const float*)d_in[9];
    const float* Wk2    = (const float*)d_in[10];
    const float* Wv     = (const float*)d_in[11];
    const float* proj_w = (const float*)d_in[12];
    const float* proj_b = (const float*)d_in[13];
    const float* gs_w   = (const float*)d_in[14];
    const float* gs_b   = (const float*)d_in[15];
    float* out = (float*)d_out;

    cudaFuncSetAttribute(matvecT, cudaFuncAttributeMaxDynamicSharedMemorySize, 70000);

    float* sc;
    cudaGetSymbolAddress((void**)&sc, g_scratch);

    // zero u1, u2 (atomic targets)
    zeroK<<<(BATCH*DM + 255) / 256, 256>>>(sc + O_U1, BATCH * DM);
    zeroK<<<(BATCH*DL + 255) / 256, 256>>>(sc + O_U2, BATCH * DL);

    // cls_s_proj = f_s_w @ cls_s + f_s_b
    matvecT<<<64, 256, BATCH*DS*4>>>(x2, (size_t)NSR * DS, f_s_w, f_s_b, sc + O_CLS_S, DM, DS);
    // q1 = Wq1 @ cls_s_proj
    matvecT<<<64, 256, BATCH*DM*4>>>(sc + O_CLS_S, DM, Wq1, nullptr, sc + O_Q1, DM, DM);
    // u1 = Wk1^T q1
    matvecC<<<dim3(DM/256, 8), 256>>>(sc + O_Q1, DM, Wk1, sc + O_U1, DM, DM);
    // cls_m_proj = f_m_w @ cls_m + f_m_b
    matvecT<<<128, 256, BATCH*DM*4>>>(x1, (size_t)NMR * DM, f_m_w, f_m_b, sc + O_CLS_M, DL, DM);
    // q2 = Wq2 @ cls_m_proj
    matvecT<<<128, 256, BATCH*DL*4>>>(sc + O_CLS_M, DL, Wq2, nullptr, sc + O_Q2, DL, DL);
    // u2 = Wk2^T q2
    matvecC<<<dim3(DL/256, 8), 256>>>(sc + O_Q2, DL, Wk2, sc + O_U2, DL, DL);
    // s1 scores + softmax
    scores1<<<dim3((NMR + 7) / 8, BATCH), 256>>>(x1);
    softmax1<<<BATCH, 256>>>();
    // att1p = att1 @ proj_w^T + proj_b
    matvecT<<<(NP + 7) / 8, 256, BATCH*((NMR+3)&~3)*4>>>(sc + O_A1, NMR, proj_w, proj_b, sc + O_ATT1P, NP, NMR);
    // fused pass over x0
    bigpass<<<dim3(DBLK, BATCH), DTHREADS>>>(x0);
    finalize<<<dim3(DL/256, BATCH), 256>>>();
    // ov = Wv @ y
    matvecT<<<128, 256, BATCH*DL*4>>>(sc + O_Y, DL, Wv, nullptr, sc + O_OV, DL, DL);
    // g_s = gs_w @ ov + gs_b
    matvecT<<<32, 256, BATCH*DL*4>>>(sc + O_OV, DL, gs_w, gs_b, sc + O_GS, DS, DL);
    // output broadcast
    broadcastOut<<<dim3(256, BATCH), 256>>>(out);
}

// round 3
// speedup vs baseline: 1.0378x; 1.0378x over previous
#include <cuda_runtime.h>
#include <math_constants.h>

#define BATCH 16
#define NL 4097      // x0 rows
#define DL 1024
#define NMR 1025     // x1 rows
#define DM 512
#define NSR 4097     // x2 rows / output rows
#define DS 256
#define NP 4098      // att1p length

#define INV_DK1 (1.0f/22.0f)
#define INV_DK2 (1.0f/32.0f)

#define DBLK 18
#define DWARPS 8
#define DTHREADS 256
#define NWARP (DBLK*DWARPS)   // 144 warp-partials per batch

// ---- scratch layout (floats) ----
#define O_CLS_S   0
#define O_Q1      8192
#define O_U1      16384
#define O_CLS_M   24576
#define O_Q2      40960
#define O_U2      57344
#define O_S1      73728
#define O_A1      90128
#define O_ATT1P   106528
#define O_Y       172096
#define O_OV      188480
#define O_GS      204864
#define O_PM      208960
#define O_PZ      (O_PM + BATCH*NWARP)
#define O_PA1     (O_PZ + BATCH*NWARP)
#define O_PA2     (O_PA1 + BATCH*NWARP*DL)
#define SCRATCH_FLOATS (O_PA2 + BATCH*NWARP*DL)

__device__ float g_scratch[SCRATCH_FLOATS];

__device__ __forceinline__ float warpSum(float v) {
    v += __shfl_xor_sync(0xffffffffu, v, 16);
    v += __shfl_xor_sync(0xffffffffu, v, 8);
    v += __shfl_xor_sync(0xffffffffu, v, 4);
    v += __shfl_xor_sync(0xffffffffu, v, 2);
    v += __shfl_xor_sync(0xffffffffu, v, 1);
    return v;
}
__device__ __forceinline__ float warpMax(float v) {
    v = fmaxf(v, __shfl_xor_sync(0xffffffffu, v, 16));
    v = fmaxf(v, __shfl_xor_sync(0xffffffffu, v, 8));
    v = fmaxf(v, __shfl_xor_sync(0xffffffffu, v, 4));
    v = fmaxf(v, __shfl_xor_sync(0xffffffffu, v, 2));
    v = fmaxf(v, __shfl_xor_sync(0xffffffffu, v, 1));
    return v;
}

__global__ void zeroK(float* p, int n) {
    int i = blockIdx.x * blockDim.x + threadIdx.x;
    if (i < n) p[i] = 0.f;
}

// y[b,n] = bias[n] + sum_k x[b*xstride+k] * W[n*K+k]  (W row-major (N,K)); warp per n.
__global__ void matvecT(const float* __restrict__ x, size_t xstride,
                        const float* __restrict__ W, const float* __restrict__ bias,
                        float* __restrict__ y, int N, int K) {
    extern __shared__ float sx[];
    const int Kp = (K + 3) & ~3;
    for (int i = threadIdx.x; i < BATCH * Kp; i += blockDim.x) {
        int b = i / Kp, k = i - b * Kp;
        sx[i] = (k < K) ? x[(size_t)b * xstride + k] : 0.f;
    }
    __syncthreads();
    const int warp = threadIdx.x >> 5, lane = threadIdx.x & 31;
    const int K4 = K >> 2;
    const bool wal = ((K & 3) == 0);
    for (int n = blockIdx.x * 8 + warp; n < N; n += gridDim.x * 8) {
        const float* Wn = W + (size_t)n * K;
        float acc[BATCH];
#pragma unroll
        for (int b = 0; b < BATCH; b++) acc[b] = 0.f;
        for (int c = lane; c < K4; c += 32) {
            float4 w4;
            if (wal) w4 = ((const float4*)Wn)[c];
            else { w4.x = Wn[4*c]; w4.y = Wn[4*c+1]; w4.z = Wn[4*c+2]; w4.w = Wn[4*c+3]; }
#pragma unroll
            for (int b = 0; b < BATCH; b++) {
                float4 xv = *(const float4*)(sx + b * Kp + 4 * c);
                acc[b] = fmaf(xv.x, w4.x, fmaf(xv.y, w4.y, fmaf(xv.z, w4.z, fmaf(xv.w, w4.w, acc[b]))));
            }
        }
        for (int k = (K4 << 2) + lane; k < K; k += 32) {
            float w = Wn[k];
#pragma unroll
            for (int b = 0; b < BATCH; b++) acc[b] = fmaf(sx[b * Kp + k], w, acc[b]);
        }
#pragma unroll
        for (int b = 0; b < BATCH; b++) {
            float v = warpSum(acc[b]);
            if (lane == 0) y[(size_t)b * N + n] = v + (bias ? bias[n] : 0.f);
        }
    }
}

// y[b,n] += sum_k x[b*xstride+k] * W[k*N+n]  (contract over W's row index).
// grid (N/256, KSPLIT); y pre-zeroed; atomic accumulate across k-splits.
#define CTK 64
__global__ void matvecC(const float* __restrict__ x, size_t xstride,
                        const float* __restrict__ W,
                        float* __restrict__ y, int N, int K) {
    __shared__ float sx[BATCH * CTK];
    const int t = threadIdx.x;
    const int n = blockIdx.x * 256 + t;
    const int KC = K / gridDim.y;
    const int kbeg = blockIdx.y * KC, kend = kbeg + KC;
    float acc[BATCH];
#pragma unroll
    for (int b = 0; b < BATCH; b++) acc[b] = 0.f;
    for (int k0 = kbeg; k0 < kend; k0 += CTK) {
        for (int i = t; i < BATCH * CTK; i += 256) {
            int b = i >> 6, kk = i & (CTK - 1);
            sx[i] = x[(size_t)b * xstride + k0 + kk];
        }
        __syncthreads();
#pragma unroll 4
        for (int kk = 0; kk < CTK; kk++) {
            float w = W[(size_t)(k0 + kk) * N + n];
#pragma unroll
            for (int b = 0; b < BATCH; b++) acc[b] = fmaf(sx[b * CTK + kk], w, acc[b]);
        }
        __syncthreads();
    }
#pragma unroll
    for (int b = 0; b < BATCH; b++) atomicAdd(&y[(size_t)b * N + n], acc[b]);
}

// s1[b,r] = dot(row_r, u1[b])/22 ; row 0 = cls_s_proj, rows 1.. = x1[b,r,:]
__global__ void scores1(const float* __restrict__ x1) {
    const int b = blockIdx.y;
    const int warp = threadIdx.x >> 5, lane = threadIdx.x & 31;
    const int r = blockIdx.x * 8 + warp;
    if (r >= NMR) return;
    const float4* xr = (r == 0)
        ? (const float4*)(g_scratch + O_CLS_S + (size_t)b * DM)
        : (const float4*)(x1 + ((size_t)b * NMR + r) * DM);
    const float4* u = (const float4*)(g_scratch + O_U1 + (size_t)b * DM);
    float acc = 0.f;
#pragma unroll
    for (int i = 0; i < DM / 128; i++) {
        float4 xv = xr[lane + 32 * i];
        float4 uv = __ldg(&u[lane + 32 * i]);
        acc += xv.x * uv.x + xv.y * uv.y + xv.z * uv.z + xv.w * uv.w;
    }
    acc = warpSum(acc);
    if (lane == 0) g_scratch[O_S1 + (size_t)b * NMR + r] = acc * INV_DK1;
}

__global__ void softmax1() {
    const int b = blockIdx.x, t = threadIdx.x;
    const float* s = g_scratch + O_S1 + (size_t)b * NMR;
    float* a = g_scratch + O_A1 + (size_t)b * NMR;
    __shared__ float red[8];
    __shared__ float sv;
    float m = -CUDART_INF_F;
    for (int i = t; i < NMR; i += 256) m = fmaxf(m, s[i]);
    m = warpMax(m);
    if ((t & 31) == 0) red[t >> 5] = m;
    __syncthreads();
    if (t == 0) { float v = red[0]; for (int i = 1; i < 8; i++) v = fmaxf(v, red[i]); sv = v; }
    __syncthreads();
    const float M = sv;
    float z = 0.f;
    for (int i = t; i < NMR; i += 256) z += __expf(s[i] - M);
    z = warpSum(z);
    __syncthreads();
    if ((t & 31) == 0) red[t >> 5] = z;
    __syncthreads();
    if (t == 0) { float v = 0.f; for (int i = 0; i < 8; i++) v += red[i]; sv = v; }
    __syncthreads();
    const float inv = 1.f / sv;
    for (int i = t; i < NMR; i += 256) a[i] = __expf(s[i] - M) * inv;
}

// Fused single pass over x0: s2 = x·u2/32 with online softmax, plus a1 += att1p[1+r]*x.
// 8 warps/block, 2 blocks/SM for 16 warps of latency hiding.
__global__ void __launch_bounds__(DTHREADS, 2) bigpass(const float* __restrict__ x0) {
    __shared__ float4 su2[DL / 4];
    const int b = blockIdx.y;
    const int t = threadIdx.x;
    if (t < DL / 4) su2[t] = ((const float4*)(g_scratch + O_U2 + (size_t)b * DL))[t];
    __syncthreads();
    const int warp = t >> 5, lane = t & 31;
    const int wid = blockIdx.x * DWARPS + warp;
    const float* attp = g_scratch + O_ATT1P + (size_t)b * NP + 1;

    float4 a1v[8], a2v[8];
#pragma unroll
    for (int i = 0; i < 8; i++) {
        a1v[i] = make_float4(0.f, 0.f, 0.f, 0.f);
        a2v[i] = make_float4(0.f, 0.f, 0.f, 0.f);
    }
    float m = -CUDART_INF_F, Z = 0.f;

    for (int r = wid; r < NL; r += NWARP) {
        const float4* xr = (const float4*)(x0 + ((size_t)b * NL + r) * DL);
        float4 xv[8];
#pragma unroll
        for (int i = 0; i < 8; i++) xv[i] = xr[lane + 32 * i];
        float s = 0.f;
#pragma unroll
        for (int i = 0; i < 8; i++) {
            float4 uv = su2[lane + 32 * i];
            s += xv[i].x * uv.x + xv[i].y * uv.y + xv[i].z * uv.z + xv[i].w * uv.w;
        }
        s = warpSum(s) * INV_DK2;
        const float w1 = __ldg(attp + r);
        if (s > m) {              // warp-uniform
            const float sc = __expf(m - s);
            Z = fmaf(Z, sc, 1.f);
            m = s;
#pragma unroll
            for (int i = 0; i < 8; i++) {
                a2v[i].x = fmaf(a2v[i].x, sc, xv[i].x);
                a2v[i].y = fmaf(a2v[i].y, sc, xv[i].y);
                a2v[i].z = fmaf(a2v[i].z, sc, xv[i].z);
                a2v[i].w = fmaf(a2v[i].w, sc, xv[i].w);
            }
        } else {
            const float p = __expf(s - m);
            Z += p;
#pragma unroll
            for (int i = 0; i < 8; i++) {
                a2v[i].x = fmaf(p, xv[i].x, a2v[i].x);
                a2v[i].y = fmaf(p, xv[i].y, a2v[i].y);
                a2v[i].z = fmaf(p, xv[i].z, a2v[i].z);
                a2v[i].w = fmaf(p, xv[i].w, a2v[i].w);
            }
        }
#pragma unroll
        for (int i = 0; i < 8; i++) {
            a1v[i].x = fmaf(w1, xv[i].x, a1v[i].x);
            a1v[i].y = fmaf(w1, xv[i].y, a1v[i].y);
            a1v[i].z = fmaf(w1, xv[i].z, a1v[i].z);
            a1v[i].w = fmaf(w1, xv[i].w, a1v[i].w);
        }
    }
    const size_t base = ((size_t)b * NWARP + wid) * DL;
    float4* pa1 = (float4*)(g_scratch + O_PA1 + base);
    float4* pa2 = (float4*)(g_scratch + O_PA2 + base);
#pragma unroll
    for (int i = 0; i < 8; i++) { pa1[lane + 32 * i] = a1v[i]; pa2[lane + 32 * i] = a2v[i]; }
    if (lane == 0) {
        g_scratch[O_PM + b * NWARP + wid] = m;
        g_scratch[O_PZ + b * NWARP + wid] = Z;
    }
}

// Combine warp partials + cls_m_proj (k=0) row; produce y[b,:]
__global__ void finalize() {
    const int b = blockIdx.y;
    const int t = threadIdx.x;
    __shared__ float spm[NWARP], ssc[NWARP];
    __shared__ float red[8];
    __shared__ float sS0, sM, sZ;
    const float* cm = g_scratch + O_CLS_M + (size_t)b * DL;
    const float* u2 = g_scratch + O_U2 + (size_t)b * DL;
    // s0 = dot(cls_m_proj, u2)/32
    float part = 0.f;
    for (int i = t; i < DL; i += 256) part += cm[i] * u2[i];
    part = warpSum(part);
    if ((t & 31) == 0) red[t >> 5] = part;
    for (int i = t; i < NWARP; i += 256) spm[i] = g_scratch[O_PM + b * NWARP + i];
    __syncthreads();
    if (t == 0) {
        float s = 0.f;
        for (int i = 0; i < 8; i++) s += red[i];
        sS0 = s * INV_DK2;
        float M = sS0;
        for (int w = 0; w < NWARP; w++) M = fmaxf(M, spm[w]);
        sM = M;
    }
    __syncthreads();
    for (int i = t; i < NWARP; i += 256) ssc[i] = __expf(spm[i] - sM);
    __syncthreads();
    if (t == 0) {
        float Z = __expf(sS0 - sM);
        for (int w = 0; w < NWARP; w++) Z += g_scratch[O_PZ + b * NWARP + w] * ssc[w];
        sZ = Z;
    }
    __syncthreads();
    const int d = blockIdx.x * 256 + t;
    const float att1p0 = g_scratch[O_ATT1P + (size_t)b * NP];
    const float cmd = cm[d];
    float a1 = att1p0 * cmd;
    float a2 = __expf(sS0 - sM) * cmd;
    const float* pa1 = g_scratch + O_PA1 + (size_t)b * NWARP * DL + d;
    const float* pa2 = g_scratch + O_PA2 + (size_t)b * NWARP * DL + d;
#pragma unroll 6
    for (int w = 0; w < NWARP; w++) {
        a1 += __ldg(pa1 + (size_t)w * DL);
        a2 = fmaf(ssc[w], __ldg(pa2 + (size_t)w * DL), a2);
    }
    g_scratch[O_Y + (size_t)b * DL + d] = 0.3f * a1 + 0.7f * (a2 / sZ);
}

__global__ void broadcastOut(float* __restrict__ out) {
    __shared__ float4 sg[64];
    const int b = blockIdx.y;
    if (threadIdx.x < 64)
        sg[threadIdx.x] = ((const float4*)(g_scratch + O_GS + (size_t)b * DS))[threadIdx.x];
    __syncthreads();
    const int total = NSR * (DS / 4);   // 262208 float4 per batch
    float4* ob = (float4*)out + (size_t)b * total;
    for (int i = blockIdx.x * 256 + threadIdx.x; i < total; i += 256 * 256)
        ob[i] = sg[i & 63];
}

extern "C" void kernel_launch(void* const* d_in, const int* in_sizes, int n_in,
                              void* d_out, int out_size) {
    (void)in_sizes; (void)n_in; (void)out_size;
    const float* x0     = (const float*)d_in[0];
    const float* x1     = (const float*)d_in[1];
    const float* x2     = (const float*)d_in[2];
    const float* f_s_w  = (const float*)d_in[3];
    const float* f_s_b  = (const float*)d_in[4];
    const float* f_m_w  = (const float*)d_in[5];
    const float* f_m_b  = (const float*)d_in[6];
    const float* Wq1    = (const float*)d_in[7];
    const float* Wk1    = (const float*)d_in[8];
    const float* Wq2    = (const float*)d_in[9];
    const float* Wk2    = (const float*)d_in[10];
    const float* Wv     = (const float*)d_in[11];
    const float* proj_w = (const float*)d_in[12];
    const float* proj_b = (const float*)d_in[13];
    const float* gs_w   = (const float*)d_in[14];
    const float* gs_b   = (const float*)d_in[15];
    float* out = (float*)d_out;

    cudaFuncSetAttribute(matvecT, cudaFuncAttributeMaxDynamicSharedMemorySize, 70000);

    float* sc;
    cudaGetSymbolAddress((void**)&sc, g_scratch);

    // one zero kernel covering U1..U2 span (everything between is overwritten before use)
    zeroK<<<(O_U2 + BATCH*DL - O_U1 + 255) / 256, 256>>>(sc + O_U1, O_U2 + BATCH*DL - O_U1);

    // cls_s_proj = f_s_w @ cls_s + f_s_b
    matvecT<<<64, 256, BATCH*DS*4>>>(x2, (size_t)NSR * DS, f_s_w, f_s_b, sc + O_CLS_S, DM, DS);
    // q1 = Wq1 @ cls_s_proj
    matvecT<<<64, 256, BATCH*DM*4>>>(sc + O_CLS_S, DM, Wq1, nullptr, sc + O_Q1, DM, DM);
    // u1 = Wk1^T q1
    matvecC<<<dim3(DM/256, 8), 256>>>(sc + O_Q1, DM, Wk1, sc + O_U1, DM, DM);
    // cls_m_proj = f_m_w @ cls_m + f_m_b
    matvecT<<<128, 256, BATCH*DM*4>>>(x1, (size_t)NMR * DM, f_m_w, f_m_b, sc + O_CLS_M, DL, DM);
    // q2 = Wq2 @ cls_m_proj
    matvecT<<<128, 256, BATCH*DL*4>>>(sc + O_CLS_M, DL, Wq2, nullptr, sc + O_Q2, DL, DL);
    // u2 = Wk2^T q2
    matvecC<<<dim3(DL/256, 8), 256>>>(sc + O_Q2, DL, Wk2, sc + O_U2, DL, DL);
    // s1 scores + softmax
    scores1<<<dim3((NMR + 7) / 8, BATCH), 256>>>(x1);
    softmax1<<<BATCH, 256>>>();
    // att1p = att1 @ proj_w^T + proj_b
    matvecT<<<(NP + 7) / 8, 256, BATCH*((NMR+3)&~3)*4>>>(sc + O_A1, NMR, proj_w, proj_b, sc + O_ATT1P, NP, NMR);
    // fused pass over x0
    bigpass<<<dim3(DBLK, BATCH), DTHREADS>>>(x0);
    finalize<<<dim3(DL/256, BATCH), 256>>>();
    // ov = Wv @ y
    matvecT<<<128, 256, BATCH*DL*4>>>(sc + O_Y, DL, Wv, nullptr, sc + O_OV, DL, DL);
    // g_s = gs_w @ ov + gs_b
    matvecT<<<32, 256, BATCH*DL*4>>>(sc + O_OV, DL, gs_w, gs_b, sc + O_GS, DS, DL);
    // output broadcast
    broadcastOut<<<dim3(256, BATCH), 256>>>(out);
}

// round 4
// speedup vs baseline: 1.5589x; 1.5022x over previous
#include <cuda_runtime.h>
#include <math_constants.h>

#define BATCH 16
#define NL 4097      // x0 rows
#define DL 1024
#define NMR 1025     // x1 rows
#define DM 512
#define NSR 4097     // x2 rows / output rows
#define DS 256
#define NP 4098      // att1p length

#define INV_DK1 (1.0f/22.0f)
#define INV_DK2 (1.0f/32.0f)

#define DBLK 18
#define DWARPS 8
#define DTHREADS 256
#define NWARP (DBLK*DWARPS)   // 144 warp-partials per batch

// ---- scratch layout (floats) ----
#define O_CLS_S   0
#define O_Q1      8192
#define O_U1      16384
#define O_CLS_M   24576
#define O_Q2      40960
#define O_U2      57344
#define O_Z1      73728                 // 16 floats (softmax1 denominators)
#define O_A1      90128                 // e = exp(s1), 16 x 1025
#define O_ATT1P   106528
#define O_Y       172096
#define O_OV      188480
#define O_GS      204864
#define O_PM      208960
#define O_PZ      (O_PM + BATCH*NWARP)
#define O_PA1     (O_PZ + BATCH*NWARP)
#define O_PA2     (O_PA1 + BATCH*NWARP*DL)
#define SCRATCH_FLOATS (O_PA2 + BATCH*NWARP*DL)

__device__ float g_scratch[SCRATCH_FLOATS];

__device__ __forceinline__ float warpSum(float v) {
    v += __shfl_xor_sync(0xffffffffu, v, 16);
    v += __shfl_xor_sync(0xffffffffu, v, 8);
    v += __shfl_xor_sync(0xffffffffu, v, 4);
    v += __shfl_xor_sync(0xffffffffu, v, 2);
    v += __shfl_xor_sync(0xffffffffu, v, 1);
    return v;
}

// ---- block-per-output matvec: y[b,n] = bias[n] + sum_k x[b*xstride+k]*W[n*K+k]
// 256 threads; K multiple of 4. All 16 batches accumulated per thread.
__device__ __forceinline__ void mv_block(const float* __restrict__ x, size_t xstride,
                                         const float* __restrict__ W,
                                         const float* __restrict__ bias,
                                         float* __restrict__ y, int N, int K, int n) {
    __shared__ float red[8][BATCH];
    const float4* Wn = (const float4*)(W + (size_t)n * K);
    const int K4 = K >> 2;
    float acc[BATCH];
#pragma unroll
    for (int b = 0; b < BATCH; b++) acc[b] = 0.f;
    for (int c = threadIdx.x; c < K4; c += 256) {
        float4 w4 = __ldg(Wn + c);
#pragma unroll
        for (int b = 0; b < BATCH; b++) {
            float4 xv = __ldg((const float4*)(x + (size_t)b * xstride) + c);
            acc[b] = fmaf(xv.x, w4.x, fmaf(xv.y, w4.y, fmaf(xv.z, w4.z, fmaf(xv.w, w4.w, acc[b]))));
        }
    }
    const int warp = threadIdx.x >> 5, lane = threadIdx.x & 31;
#pragma unroll
    for (int b = 0; b < BATCH; b++) acc[b] = warpSum(acc[b]);
    if (lane == 0) {
#pragma unroll
        for (int b = 0; b < BATCH; b++) red[warp][b] = acc[b];
    }
    __syncthreads();
    if (threadIdx.x < BATCH) {
        float s = 0.f;
#pragma unroll
        for (int w = 0; w < 8; w++) s += red[w][threadIdx.x];
        y[(size_t)threadIdx.x * N + n] = s + (bias ? bias[n] : 0.f);
    }
}

// depth 0: cls_s_proj (512) + cls_m_proj (1024) + zero u1/u2/Z1
#define NZERO (BATCH*DM + BATCH*DL + BATCH)
__global__ void prepK(const float* __restrict__ x1, const float* __restrict__ x2,
                      const float* __restrict__ f_s_w, const float* __restrict__ f_s_b,
                      const float* __restrict__ f_m_w, const float* __restrict__ f_m_b) {
    const int bx = blockIdx.x;
    if (bx < DM) {
        mv_block(x2, (size_t)NSR * DS, f_s_w, f_s_b, g_scratch + O_CLS_S, DM, DS, bx);
    } else if (bx < DM + DL) {
        mv_block(x1, (size_t)NMR * DM, f_m_w, f_m_b, g_scratch + O_CLS_M, DL, DM, bx - DM);
    } else {
        const int zb = bx - (DM + DL);   // 0..31
        for (int i = zb * 256 + threadIdx.x; i < NZERO; i += 32 * 256) {
            int j = (i < BATCH * DM) ? (O_U1 + i)
                  : (i < BATCH * (DM + DL)) ? (O_U2 + i - BATCH * DM)
                  : (O_Z1 + i - BATCH * (DM + DL));
            g_scratch[j] = 0.f;
        }
    }
}

// depth 1: q1 = Wq1 @ cls_s_proj ; q2 = Wq2 @ cls_m_proj
__global__ void qK(const float* __restrict__ Wq1, const float* __restrict__ Wq2) {
    const int bx = blockIdx.x;
    if (bx < DM)
        mv_block(g_scratch + O_CLS_S, DM, Wq1, nullptr, g_scratch + O_Q1, DM, DM, bx);
    else
        mv_block(g_scratch + O_CLS_M, DL, Wq2, nullptr, g_scratch + O_Q2, DL, DL, bx - DM);
}

// depth 2: u1 = Wk1^T q1 ; u2 = Wk2^T q2   (grid (6,16): bx<2 -> u1, else u2)
__global__ void uK(const float* __restrict__ Wk1, const float* __restrict__ Wk2) {
    const int bx = blockIdx.x, ks = blockIdx.y;   // 16 k-splits
    const float* W;  const float* x;  float* y;
    int N, K, n;
    if (bx < 2) { W = Wk1; x = g_scratch + O_Q1; y = g_scratch + O_U1; N = DM; K = DM; n = bx * 256 + threadIdx.x; }
    else        { W = Wk2; x = g_scratch + O_Q2; y = g_scratch + O_U2; N = DL; K = DL; n = (bx - 2) * 256 + threadIdx.x; }
    const int chunk = K >> 4;
    const int kbeg = ks * chunk;
    float acc[BATCH];
#pragma unroll
    for (int b = 0; b < BATCH; b++) acc[b] = 0.f;
#pragma unroll 4
    for (int kk = kbeg; kk < kbeg + chunk; kk++) {
        float w = __ldg(W + (size_t)kk * N + n);
#pragma unroll
        for (int b = 0; b < BATCH; b++) acc[b] = fmaf(__ldg(x + (size_t)b * K + kk), w, acc[b]);
    }
#pragma unroll
    for (int b = 0; b < BATCH; b++) atomicAdd(&y[(size_t)b * N + n], acc[b]);
}

// depth 3: e[b,r] = exp(dot(row_r,u1[b])/22); Z1[b] += e. Scores are O(0.3) -> exp safe.
__global__ void scoresE(const float* __restrict__ x1) {
    const int b = blockIdx.y;
    const int warp = threadIdx.x >> 5, lane = threadIdx.x & 31;
    const int r = blockIdx.x * 8 + warp;
    if (r >= NMR) return;
    const float4* xr = (r == 0)
        ? (const float4*)(g_scratch + O_CLS_S + (size_t)b * DM)
        : (const float4*)(x1 + ((size_t)b * NMR + r) * DM);
    const float4* u = (const float4*)(g_scratch + O_U1 + (size_t)b * DM);
    float acc = 0.f;
#pragma unroll
    for (int i = 0; i < DM / 128; i++) {
        float4 xv = __ldg(&xr[lane + 32 * i]);
        float4 uv = __ldg(&u[lane + 32 * i]);
        acc += xv.x * uv.x + xv.y * uv.y + xv.z * uv.z + xv.w * uv.w;
    }
    acc = warpSum(acc);
    if (lane == 0) {
        float e = __expf(acc * INV_DK1);
        g_scratch[O_A1 + (size_t)b * NMR + r] = e;
        atomicAdd(&g_scratch[O_Z1 + b], e);
    }
}

// depth 4: att1p[b,n] = (sum_k e[b,k]*proj_w[n,k]) / Z1[b] + proj_b[n]. warp per n.
__global__ void att1pK(const float* __restrict__ W, const float* __restrict__ bias) {
    extern __shared__ float sx[];
    const int Kp = (NMR + 3) & ~3;   // 1028
    for (int i = threadIdx.x; i < BATCH * Kp; i += blockDim.x) {
        int b = i / Kp, k = i - b * Kp;
        sx[i] = (k < NMR) ? g_scratch[O_A1 + (size_t)b * NMR + k] : 0.f;
    }
    __syncthreads();
    const int warp = threadIdx.x >> 5, lane = threadIdx.x & 31;
    const int n = blockIdx.x * 8 + warp;
    if (n >= NP) return;
    const float* Wn = W + (size_t)n * NMR;
    const int K4 = NMR >> 2;   // 256
    float acc[BATCH];
#pragma unroll
    for (int b = 0; b < BATCH; b++) acc[b] = 0.f;
    for (int c = lane; c < K4; c += 32) {
        float w0 = __ldg(Wn + 4*c), w1 = __ldg(Wn + 4*c+1), w2 = __ldg(Wn + 4*c+2), w3 = __ldg(Wn + 4*c+3);
#pragma unroll
        for (int b = 0; b < BATCH; b++) {
            float4 xv = *(const float4*)(sx + b * Kp + 4 * c);
            acc[b] = fmaf(xv.x, w0, fmaf(xv.y, w1, fmaf(xv.z, w2, fmaf(xv.w, w3, acc[b]))));
        }
    }
    if (lane == 0) {   // tail k = 1024
        float w = __ldg(Wn + 1024);
#pragma unroll
        for (int b = 0; b < BATCH; b++) acc[b] = fmaf(sx[b * Kp + 1024], w, acc[b]);
    }
#pragma unroll
    for (int b = 0; b < BATCH; b++) {
        float v = warpSum(acc[b]);
        if (lane == 0)
            g_scratch[O_ATT1P + (size_t)b * NP + n] = v / g_scratch[O_Z1 + b] + bias[n];
    }
}

// depth 5: fused single pass over x0 (online softmax for att2 + att1-weighted sum).
__global__ void __launch_bounds__(DTHREADS, 2) bigpass(const float* __restrict__ x0) {
    __shared__ float4 su2[DL / 4];
    const int b = blockIdx.y;
    const int t = threadIdx.x;
    su2[t] = ((const float4*)(g_scratch + O_U2 + (size_t)b * DL))[t];
    __syncthreads();
    const int warp = t >> 5, lane = t & 31;
    const int wid = blockIdx.x * DWARPS + warp;
    const float* attp = g_scratch + O_ATT1P + (size_t)b * NP + 1;

    float4 a1v[8], a2v[8];
#pragma unroll
    for (int i = 0; i < 8; i++) {
        a1v[i] = make_float4(0.f, 0.f, 0.f, 0.f);
        a2v[i] = make_float4(0.f, 0.f, 0.f, 0.f);
    }
    float m = -CUDART_INF_F, Z = 0.f;

    for (int r = wid; r < NL; r += NWARP) {
        const float4* xr = (const float4*)(x0 + ((size_t)b * NL + r) * DL);
        float4 xv[8];
#pragma unroll
        for (int i = 0; i < 8; i++) xv[i] = xr[lane + 32 * i];
        float s = 0.f;
#pragma unroll
        for (int i = 0; i < 8; i++) {
            float4 uv = su2[lane + 32 * i];
            s += xv[i].x * uv.x + xv[i].y * uv.y + xv[i].z * uv.z + xv[i].w * uv.w;
        }
        s = warpSum(s) * INV_DK2;
        const float w1 = __ldg(attp + r);
        if (s > m) {
            const float sc = __expf(m - s);
            Z = fmaf(Z, sc, 1.f);
            m = s;
#pragma unroll
            for (int i = 0; i < 8; i++) {
                a2v[i].x = fmaf(a2v[i].x, sc, xv[i].x);
                a2v[i].y = fmaf(a2v[i].y, sc, xv[i].y);
                a2v[i].z = fmaf(a2v[i].z, sc, xv[i].z);
                a2v[i].w = fmaf(a2v[i].w, sc, xv[i].w);
            }
        } else {
            const float p = __expf(s - m);
            Z += p;
#pragma unroll
            for (int i = 0; i < 8; i++) {
                a2v[i].x = fmaf(p, xv[i].x, a2v[i].x);
                a2v[i].y = fmaf(p, xv[i].y, a2v[i].y);
                a2v[i].z = fmaf(p, xv[i].z, a2v[i].z);
                a2v[i].w = fmaf(p, xv[i].w, a2v[i].w);
            }
        }
#pragma unroll
        for (int i = 0; i < 8; i++) {
            a1v[i].x = fmaf(w1, xv[i].x, a1v[i].x);
            a1v[i].y = fmaf(w1, xv[i].y, a1v[i].y);
            a1v[i].z = fmaf(w1, xv[i].z, a1v[i].z);
            a1v[i].w = fmaf(w1, xv[i].w, a1v[i].w);
        }
    }
    const size_t base = ((size_t)b * NWARP + wid) * DL;
    float4* pa1 = (float4*)(g_scratch + O_PA1 + base);
    float4* pa2 = (float4*)(g_scratch + O_PA2 + base);
#pragma unroll
    for (int i = 0; i < 8; i++) { pa1[lane + 32 * i] = a1v[i]; pa2[lane + 32 * i] = a2v[i]; }
    if (lane == 0) {
        g_scratch[O_PM + b * NWARP + wid] = m;
        g_scratch[O_PZ + b * NWARP + wid] = Z;
    }
}

// depth 6: combine warp partials + cls_m_proj (k=0) row -> y[b,:]
__global__ void finalize() {
    const int b = blockIdx.y;
    const int t = threadIdx.x;
    __shared__ float spm[NWARP], ssc[NWARP];
    __shared__ float red[8];
    __shared__ float sS0, sM, sZ;
    const float* cm = g_scratch + O_CLS_M + (size_t)b * DL;
    const float* u2 = g_scratch + O_U2 + (size_t)b * DL;
    float part = 0.f;
    for (int i = t; i < DL; i += 256) part += cm[i] * u2[i];
    part = warpSum(part);
    if ((t & 31) == 0) red[t >> 5] = part;
    for (int i = t; i < NWARP; i += 256) spm[i] = g_scratch[O_PM + b * NWARP + i];
    __syncthreads();
    if (t == 0) {
        float s = 0.f;
        for (int i = 0; i < 8; i++) s += red[i];
        sS0 = s * INV_DK2;
        float M = sS0;
        for (int w = 0; w < NWARP; w++) M = fmaxf(M, spm[w]);
        sM = M;
    }
    __syncthreads();
    for (int i = t; i < NWARP; i += 256) ssc[i] = __expf(spm[i] - sM);
    __syncthreads();
    if (t == 0) {
        float Z = __expf(sS0 - sM);
        for (int w = 0; w < NWARP; w++) Z += g_scratch[O_PZ + b * NWARP + w] * ssc[w];
        sZ = Z;
    }
    __syncthreads();
    const int d = blockIdx.x * 256 + t;
    const float att1p0 = g_scratch[O_ATT1P + (size_t)b * NP];
    const float cmd = cm[d];
    float a1 = att1p0 * cmd;
    float a2 = __expf(sS0 - sM) * cmd;
    const float* pa1 = g_scratch + O_PA1 + (size_t)b * NWARP * DL + d;
    const float* pa2 = g_scratch + O_PA2 + (size_t)b * NWARP * DL + d;
#pragma unroll 6
    for (int w = 0; w < NWARP; w++) {
        a1 += __ldg(pa1 + (size_t)w * DL);
        a2 = fmaf(ssc[w], __ldg(pa2 + (size_t)w * DL), a2);
    }
    g_scratch[O_Y + (size_t)b * DL + d] = 0.3f * a1 + 0.7f * (a2 / sZ);
}

// depth 7: ov = Wv @ y
__global__ void ovK(const float* __restrict__ Wv) {
    mv_block(g_scratch + O_Y, DL, Wv, nullptr, g_scratch + O_OV, DL, DL, blockIdx.x);
}
// depth 8: g_s = gs_w @ ov + gs_b
__global__ void gsK(const float* __restrict__ gs_w, const float* __restrict__ gs_b) {
    mv_block(g_scratch + O_OV, DL, gs_w, gs_b, g_scratch + O_GS, DS, DL, blockIdx.x);
}

// depth 9: out[b, r, :] = g_s[b] for all 4097 rows
__global__ void broadcastOut(float* __restrict__ out) {
    __shared__ float4 sg[64];
    const int b = blockIdx.y;
    if (threadIdx.x < 64)
        sg[threadIdx.x] = ((const float4*)(g_scratch + O_GS + (size_t)b * DS))[threadIdx.x];
    __syncthreads();
    const int total = NSR * (DS / 4);
    float4* ob = (float4*)out + (size_t)b * total;
    for (int i = blockIdx.x * 256 + threadIdx.x; i < total; i += 256 * 256)
        ob[i] = sg[i & 63];
}

extern "C" void kernel_launch(void* const* d_in, const int* in_sizes, int n_in,
                              void* d_out, int out_size) {
    (void)in_sizes; (void)n_in; (void)out_size;
    const float* x0     = (const float*)d_in[0];
    const float* x1     = (const float*)d_in[1];
    const float* x2     = (const float*)d_in[2];
    const float* f_s_w  = (const float*)d_in[3];
    const float* f_s_b  = (const float*)d_in[4];
    const float* f_m_w  = (const float*)d_in[5];
    const float* f_m_b  = (const float*)d_in[6];
    const float* Wq1    = (const float*)d_in[7];
    const float* Wk1    = (const float*)d_in[8];
    const float* Wq2    = (const float*)d_in[9];
    const float* Wk2    = (const float*)d_in[10];
    const float* Wv     = (const float*)d_in[11];
    const float* proj_w = (const float*)d_in[12];
    const float* proj_b = (const float*)d_in[13];
    const float* gs_w   = (const float*)d_in[14];
    const float* gs_b   = (const float*)d_in[15];
    float* out = (float*)d_out;

    cudaFuncSetAttribute(att1pK, cudaFuncAttributeMaxDynamicSharedMemorySize, 70000);

    prepK<<<DM + DL + 32, 256>>>(x1, x2, f_s_w, f_s_b, f_m_w, f_m_b);
    qK<<<DM + DL, 256>>>(Wq1, Wq2);
    uK<<<dim3(6, 16), 256>>>(Wk1, Wk2);
    scoresE<<<dim3((NMR + 7) / 8, BATCH), 256>>>(x1);
    att1pK<<<(NP + 7) / 8, 256, BATCH * ((NMR + 3) & ~3) * 4>>>(proj_w, proj_b);
    bigpass<<<dim3(DBLK, BATCH), DTHREADS>>>(x0);
    finalize<<<dim3(DL / 256, BATCH), 256>>>();
    ovK<<<DL, 256>>>(Wv);
    gsK<<<DS, 256>>>(gs_w, gs_b);
    broadcastOut<<<dim3(256, BATCH), 256>>>(out);
}